// round 1
// baseline (speedup 1.0000x reference)
#include <cuda_runtime.h>
#include <cstdint>

// Embedding gather with even-token-id remap to 0.
// x: [B*S] int32 token ids; emb: [VOCAB, EMB] fp32; out: [B*S, EMB] fp32.
// EMB = 512 floats = 128 float4 per row.

static constexpr int EMB = 512;
static constexpr int VEC_PER_ROW = EMB / 4;  // 128

__global__ __launch_bounds__(128)
void embed_gather_kernel(const int* __restrict__ x,
                         const float4* __restrict__ emb,
                         float4* __restrict__ out,
                         int n_rows) {
    int row = blockIdx.x;
    if (row >= n_rows) return;

    int tok = x[row];
    // even ids -> 0 (reference: jnp.where(x % 2 == 0, 0, x))
    tok = (tok & 1) ? tok : 0;

    const float4* src = emb + (size_t)tok * VEC_PER_ROW;
    float4* dst = out + (size_t)row * VEC_PER_ROW;

    int t = threadIdx.x;  // 0..127, one float4 each
    dst[t] = __ldg(src + t);
}

extern "C" void kernel_launch(void* const* d_in, const int* in_sizes, int n_in,
                              void* d_out, int out_size) {
    const int* x = (const int*)d_in[0];
    const float4* emb = (const float4*)d_in[1];
    float4* out = (float4*)d_out;

    int n_rows = in_sizes[0];  // B*S = 32768

    embed_gather_kernel<<<n_rows, 128>>>(x, emb, out, n_rows);
}

// round 2
// speedup vs baseline: 1.4396x; 1.4396x over previous
#include <cuda_runtime.h>
#include <cstdint>

// Embedding gather with even-token-id remap to 0.
// x: [B*S] int32; emb: [VOCAB, 512] fp32; out: [B*S, 512] fp32.
// 512 floats = 128 float4 per row.
//
// Latency-hiding layout: 256 threads/CTA, 16 rows/CTA.
// Each thread copies 8 independent float4s (MLP=8).

static constexpr int VEC_PER_ROW = 128;        // float4 per row
static constexpr int ROWS_PER_BLOCK = 16;
static constexpr int THREADS = 256;
static constexpr int CHUNKS = ROWS_PER_BLOCK * VEC_PER_ROW / THREADS;  // 8

__global__ __launch_bounds__(THREADS)
void embed_gather_kernel(const int* __restrict__ x,
                         const float4* __restrict__ emb,
                         float4* __restrict__ out,
                         int n_rows) {
    __shared__ int toks[ROWS_PER_BLOCK];

    int base_row = blockIdx.x * ROWS_PER_BLOCK;
    int tid = threadIdx.x;

    if (tid < ROWS_PER_BLOCK) {
        int r = base_row + tid;
        int tok = (r < n_rows) ? x[r] : 0;
        // even ids -> 0 (reference: jnp.where(x % 2 == 0, 0, x))
        toks[tid] = (tok & 1) ? tok : 0;
    }
    __syncthreads();

    // Block-local flat float4 index space: ROWS_PER_BLOCK * 128 elements.
    // chunk c covers [c*256, c*256+256); thread handles element c*256 + tid.
    float4* dst = out + (size_t)base_row * VEC_PER_ROW;

    float4 v[CHUNKS];
#pragma unroll
    for (int c = 0; c < CHUNKS; c++) {
        int i = c * THREADS + tid;
        int r = i >> 7;           // / 128
        int col = i & 127;
        v[c] = __ldg(emb + (size_t)toks[r] * VEC_PER_ROW + col);
    }
#pragma unroll
    for (int c = 0; c < CHUNKS; c++) {
        int i = c * THREADS + tid;
        dst[i] = v[c];
    }
}

extern "C" void kernel_launch(void* const* d_in, const int* in_sizes, int n_in,
                              void* d_out, int out_size) {
    const int* x = (const int*)d_in[0];
    const float4* emb = (const float4*)d_in[1];
    float4* out = (float4*)d_out;

    int n_rows = in_sizes[0];  // 32768
    int n_blocks = (n_rows + ROWS_PER_BLOCK - 1) / ROWS_PER_BLOCK;  // 2048

    embed_gather_kernel<<<n_blocks, THREADS>>>(x, emb, out, n_rows);
}

// round 3
// speedup vs baseline: 1.5702x; 1.0907x over previous
#include <cuda_runtime.h>
#include <cstdint>

// Embedding gather with even-token-id remap to 0.
// x: [B*S] int32; emb: [VOCAB, 512] fp32; out: [B*S, 512] fp32.
// 512 floats = 128 float4 per row.
//
// 256 threads/CTA, 16 rows/CTA, 8 independent float4 copies per thread.
// Compiler barrier between load and store phases forces all 8 LDG.128s
// to be in flight simultaneously (MLP=8), instead of ptxas pipelining
// load/store pairs with a 32-reg budget.

static constexpr int VEC_PER_ROW = 128;        // float4 per row
static constexpr int ROWS_PER_BLOCK = 16;
static constexpr int THREADS = 256;
static constexpr int CHUNKS = ROWS_PER_BLOCK * VEC_PER_ROW / THREADS;  // 8

__global__ __launch_bounds__(THREADS)
void embed_gather_kernel(const int* __restrict__ x,
                         const float4* __restrict__ emb,
                         float4* __restrict__ out,
                         int n_rows) {
    __shared__ int toks[ROWS_PER_BLOCK];

    int base_row = blockIdx.x * ROWS_PER_BLOCK;
    int tid = threadIdx.x;

    if (tid < ROWS_PER_BLOCK) {
        int r = base_row + tid;
        int tok = (r < n_rows) ? x[r] : 0;
        // even ids -> 0 (reference: jnp.where(x % 2 == 0, 0, x))
        toks[tid] = (tok & 1) ? tok : 0;
    }
    __syncthreads();

    float4* dst = out + (size_t)base_row * VEC_PER_ROW;

    float4 v0, v1, v2, v3, v4, v5, v6, v7;
    {
        // chunk c: flat index c*256 + tid; row = idx>>7, col = idx&127
        int i0 = 0 * THREADS + tid;
        int i1 = 1 * THREADS + tid;
        int i2 = 2 * THREADS + tid;
        int i3 = 3 * THREADS + tid;
        int i4 = 4 * THREADS + tid;
        int i5 = 5 * THREADS + tid;
        int i6 = 6 * THREADS + tid;
        int i7 = 7 * THREADS + tid;
        v0 = __ldg(emb + (size_t)toks[i0 >> 7] * VEC_PER_ROW + (i0 & 127));
        v1 = __ldg(emb + (size_t)toks[i1 >> 7] * VEC_PER_ROW + (i1 & 127));
        v2 = __ldg(emb + (size_t)toks[i2 >> 7] * VEC_PER_ROW + (i2 & 127));
        v3 = __ldg(emb + (size_t)toks[i3 >> 7] * VEC_PER_ROW + (i3 & 127));
        v4 = __ldg(emb + (size_t)toks[i4 >> 7] * VEC_PER_ROW + (i4 & 127));
        v5 = __ldg(emb + (size_t)toks[i5 >> 7] * VEC_PER_ROW + (i5 & 127));
        v6 = __ldg(emb + (size_t)toks[i6 >> 7] * VEC_PER_ROW + (i6 & 127));
        v7 = __ldg(emb + (size_t)toks[i7 >> 7] * VEC_PER_ROW + (i7 & 127));
    }

    // Keep all 8 loads live: don't let ptxas sink stores between loads.
    asm volatile("" ::: "memory");

    dst[0 * THREADS + tid] = v0;
    dst[1 * THREADS + tid] = v1;
    dst[2 * THREADS + tid] = v2;
    dst[3 * THREADS + tid] = v3;
    dst[4 * THREADS + tid] = v4;
    dst[5 * THREADS + tid] = v5;
    dst[6 * THREADS + tid] = v6;
    dst[7 * THREADS + tid] = v7;
}

extern "C" void kernel_launch(void* const* d_in, const int* in_sizes, int n_in,
                              void* d_out, int out_size) {
    const int* x = (const int*)d_in[0];
    const float4* emb = (const float4*)d_in[1];
    float4* out = (float4*)d_out;

    int n_rows = in_sizes[0];  // 32768
    int n_blocks = (n_rows + ROWS_PER_BLOCK - 1) / ROWS_PER_BLOCK;  // 2048

    embed_gather_kernel<<<n_blocks, THREADS>>>(x, emb, out, n_rows);
}